// round 5
// baseline (speedup 1.0000x reference)
#include <cuda_runtime.h>
#include <cstdint>

#define NV   4096
#define DV   512
#define F1V  64
#define HV   4
#define HF   256   // H*F1
#define MAXNZ 128
#define ALPHA 0.2f

// ---------------- scratch (device globals; no allocs allowed) ----------------
__device__ int   g_col[NV * MAXNZ];
__device__ int   g_cnt[NV];
__device__ float g_Whcat[NV * HF];   // x @ W_heads (head h in cols [h*64,(h+1)*64))
__device__ float g_cat[NV * HF];     // multi-head GAT output (elu'd, concat)
__device__ float g_Whc[NV * F1V];    // cat @ W_att
__device__ float g_el[NV * HV];      // [i][h] float4-friendly
__device__ float g_er[NV * HV];
__device__ float g_el2[NV];
__device__ float g_er2[NV];
__device__ float g_t1[NV * 32];
__device__ float g_t23[NV * 32];     // [mu-pre | logvar-pre] per row (16+16)
__device__ float g_z[NV * 16];

// ---------------- f32x2 packed-FMA helpers (ptxas won't auto-fuse) -----------
__device__ __forceinline__ unsigned long long pack2(float lo, float hi) {
    unsigned long long r;
    asm("mov.b64 %0, {%1, %2};" : "=l"(r) : "f"(lo), "f"(hi));
    return r;
}
__device__ __forceinline__ void ffma2(unsigned long long& d, unsigned long long a,
                                      unsigned long long b) {
    asm("fma.rn.f32x2 %0, %1, %2, %0;" : "+l"(d) : "l"(a), "l"(b));
}
__device__ __forceinline__ float2 unpack2(unsigned long long v) {
    float2 f;
    asm("mov.b64 {%0, %1}, %2;" : "=f"(f.x), "=f"(f.y) : "l"(v));
    return f;
}

// ---------------- CSR build: warp per row, float4 stream ---------------------
__global__ void k_csr(const float* __restrict__ adj) {
    int wid = threadIdx.x >> 5, lane = threadIdx.x & 31;
    int row = blockIdx.x * 8 + wid;
    const float4* r4 = (const float4*)(adj + (size_t)row * NV);
    unsigned lm = (1u << lane) - 1u;
    int base = 0;
    int* cp = g_col + row * MAXNZ;
#pragma unroll 4
    for (int c0 = 0; c0 < NV / 4; c0 += 32) {
        float4 v = r4[c0 + lane];
        unsigned b0 = __ballot_sync(0xffffffffu, v.x > 0.f);
        unsigned b1 = __ballot_sync(0xffffffffu, v.y > 0.f);
        unsigned b2 = __ballot_sync(0xffffffffu, v.z > 0.f);
        unsigned b3 = __ballot_sync(0xffffffffu, v.w > 0.f);
        int t0 = __popc(b0), t1 = __popc(b1), t2 = __popc(b2), t3 = __popc(b3);
        int col = (c0 + lane) * 4;
        if (v.x > 0.f) { int p = base + __popc(b0 & lm);                if (p < MAXNZ) cp[p] = col; }
        if (v.y > 0.f) { int p = base + t0 + __popc(b1 & lm);           if (p < MAXNZ) cp[p] = col + 1; }
        if (v.z > 0.f) { int p = base + t0 + t1 + __popc(b2 & lm);      if (p < MAXNZ) cp[p] = col + 2; }
        if (v.w > 0.f) { int p = base + t0 + t1 + t2 + __popc(b3 & lm); if (p < MAXNZ) cp[p] = col + 3; }
        base += t0 + t1 + t2 + t3;
    }
    if (lane == 0) g_cnt[row] = (base < MAXNZ) ? base : MAXNZ;
}

// ---------------- GEMM 64x64 tile + fused el/er epilogue ---------------------
// C[m0:m0+64, coff:coff+64] = A[M,K] @ B[K,64] ; el/er = C_tile @ a[:64]/a[64:]
__global__ __launch_bounds__(128) void k_gemm(const float* __restrict__ A,
                                              const float* __restrict__ Bbase,
                                              float* __restrict__ Cbase,
                                              int K, int ldc, int bstride, int ccoloff,
                                              const float* __restrict__ avec, int avstride,
                                              float* __restrict__ el_out,
                                              float* __restrict__ er_out, int estr) {
    int h = blockIdx.y;
    const float* B = Bbase + (size_t)h * bstride;
    int m0 = blockIdx.x * 64;
    int tid = threadIdx.x;
    int tx = tid & 15, ty = tid >> 4;
    __shared__ float As[16][64];
    __shared__ float Bs[16][64];
    unsigned long long acc2[8][2] = {};
    for (int k0 = 0; k0 < K; k0 += 16) {
#pragma unroll
        for (int t = tid; t < 256; t += 128) {
            int r = t >> 2, c4 = (t & 3) * 4;
            float4 v = *(const float4*)(A + (size_t)(m0 + r) * K + k0 + c4);
            As[c4][r] = v.x; As[c4 + 1][r] = v.y; As[c4 + 2][r] = v.z; As[c4 + 3][r] = v.w;
        }
#pragma unroll
        for (int t = tid; t < 256; t += 128) {
            int r = t >> 4, c = (t & 15) * 4;
            *(float4*)&Bs[r][c] = *(const float4*)(B + (size_t)(k0 + r) * 64 + c);
        }
        __syncthreads();
#pragma unroll
        for (int kk = 0; kk < 16; kk++) {
            float4 b = *(float4*)&Bs[kk][tx * 4];
            unsigned long long b01 = pack2(b.x, b.y), b23 = pack2(b.z, b.w);
            float4 a0 = *(float4*)&As[kk][ty * 8];
            float4 a1 = *(float4*)&As[kk][ty * 8 + 4];
            float av[8] = {a0.x, a0.y, a0.z, a0.w, a1.x, a1.y, a1.z, a1.w};
#pragma unroll
            for (int i = 0; i < 8; i++) {
                unsigned long long ai = pack2(av[i], av[i]);
                ffma2(acc2[i][0], ai, b01);
                ffma2(acc2[i][1], ai, b23);
            }
        }
        __syncthreads();
    }
    int coff = h * ccoloff;
    float4 aL = *(const float4*)(avec + (size_t)h * avstride + tx * 4);
    float4 aR = *(const float4*)(avec + (size_t)h * avstride + 64 + tx * 4);
#pragma unroll
    for (int i = 0; i < 8; i++) {
        float2 c0 = unpack2(acc2[i][0]), c1 = unpack2(acc2[i][1]);
        *(float4*)(Cbase + (size_t)(m0 + ty * 8 + i) * ldc + coff + tx * 4)
            = make_float4(c0.x, c0.y, c1.x, c1.y);
        float sl = c0.x * aL.x + c0.y * aL.y + c1.x * aL.z + c1.y * aL.w;
        float sr = c0.x * aR.x + c0.y * aR.y + c1.x * aR.z + c1.y * aR.w;
#pragma unroll
        for (int o = 8; o > 0; o >>= 1) {
            sl += __shfl_xor_sync(0xffffffffu, sl, o);
            sr += __shfl_xor_sync(0xffffffffu, sr, o);
        }
        if (tx == 0) {
            int row = m0 + ty * 8 + i;
            el_out[row * estr + h] = sl;
            er_out[row * estr + h] = sr;
        }
    }
}

// ---------------- 4-head GAT: softmax over neighbors + aggregate + elu -------
__global__ __launch_bounds__(256) void k_gat4(const float* __restrict__ Wh,
                                              const float* __restrict__ el4p,
                                              const float* __restrict__ er4p,
                                              float* __restrict__ out) {
    int i = blockIdx.x;
    __shared__ int cols_s[MAXNZ];
    __shared__ float ew[4][MAXNZ];
    __shared__ float4 red[256];
    int cnt = g_cnt[i];
    int tid = threadIdx.x;
    float4 eli = ((const float4*)el4p)[i];
    for (int k = tid; k < cnt; k += 256) cols_s[k] = g_col[i * MAXNZ + k];
    __syncthreads();
    for (int k = tid; k < cnt; k += 256) {
        float4 er4 = ((const float4*)er4p)[cols_s[k]];
        float e0 = eli.x + er4.x, e1 = eli.y + er4.y, e2 = eli.z + er4.z, e3 = eli.w + er4.w;
        ew[0][k] = (e0 >= 0.f) ? e0 : ALPHA * e0;
        ew[1][k] = (e1 >= 0.f) ? e1 : ALPHA * e1;
        ew[2][k] = (e2 >= 0.f) ? e2 : ALPHA * e2;
        ew[3][k] = (e3 >= 0.f) ? e3 : ALPHA * e3;
    }
    __syncthreads();
    int wid = tid >> 5, lane = tid & 31;
    if (wid < 4) {
        float m = -1e30f;
        for (int k = lane; k < cnt; k += 32) m = fmaxf(m, ew[wid][k]);
#pragma unroll
        for (int o = 16; o > 0; o >>= 1) m = fmaxf(m, __shfl_xor_sync(0xffffffffu, m, o));
        float s = 0.f;
        for (int k = lane; k < cnt; k += 32) {
            float v = __expf(ew[wid][k] - m);
            ew[wid][k] = v; s += v;
        }
#pragma unroll
        for (int o = 16; o > 0; o >>= 1) s += __shfl_xor_sync(0xffffffffu, s, o);
        float inv = 1.f / s;
        for (int k = lane; k < cnt; k += 32) ew[wid][k] *= inv;
    }
    __syncthreads();
    int q = tid & 63;          // float4 column
    int p = tid >> 6;          // phase 0..3
    int h = q >> 4;
    const float4* Wh4 = (const float4*)Wh;
    float4 aa = make_float4(0.f, 0.f, 0.f, 0.f);
    float4 ab = make_float4(0.f, 0.f, 0.f, 0.f);
    int k = p;
    for (; k + 4 < cnt; k += 8) {
        float wa = ew[h][k];
        float4 va = Wh4[(size_t)cols_s[k] * 64 + q];
        float wb = ew[h][k + 4];
        float4 vb = Wh4[(size_t)cols_s[k + 4] * 64 + q];
        aa.x += wa * va.x; aa.y += wa * va.y; aa.z += wa * va.z; aa.w += wa * va.w;
        ab.x += wb * vb.x; ab.y += wb * vb.y; ab.z += wb * vb.z; ab.w += wb * vb.w;
    }
    if (k < cnt) {
        float wa = ew[h][k];
        float4 va = Wh4[(size_t)cols_s[k] * 64 + q];
        aa.x += wa * va.x; aa.y += wa * va.y; aa.z += wa * va.z; aa.w += wa * va.w;
    }
    aa.x += ab.x; aa.y += ab.y; aa.z += ab.z; aa.w += ab.w;
    red[tid] = aa;
    __syncthreads();
    if (tid < 64) {
        float4 a = red[tid], b = red[tid + 64], c = red[tid + 128], d = red[tid + 192];
        float4 s = make_float4(a.x + b.x + c.x + d.x, a.y + b.y + c.y + d.y,
                               a.z + b.z + c.z + d.z, a.w + b.w + c.w + d.w);
        s.x = (s.x > 0.f) ? s.x : (__expf(s.x) - 1.f);
        s.y = (s.y > 0.f) ? s.y : (__expf(s.y) - 1.f);
        s.z = (s.z > 0.f) ? s.z : (__expf(s.z) - 1.f);
        s.w = (s.w > 0.f) ? s.w : (__expf(s.w) - 1.f);
        ((float4*)out)[(size_t)i * 64 + tid] = s;
    }
}

// ---------------- att GAT (1 head) fused with t1 = gc @ W1 -------------------
__global__ __launch_bounds__(64) void k_gat1(const float* __restrict__ Wh,
                                             const float* __restrict__ el2,
                                             const float* __restrict__ er2,
                                             const float* __restrict__ W1) {
    int i = blockIdx.x;
    __shared__ int cols_s[MAXNZ];
    __shared__ float ew[MAXNZ];
    __shared__ float4 red[64];
    __shared__ float gcs[64];
    int cnt = g_cnt[i];
    int tid = threadIdx.x;
    float eli = el2[i];
    for (int k = tid; k < cnt; k += 64) cols_s[k] = g_col[i * MAXNZ + k];
    __syncthreads();
    for (int k = tid; k < cnt; k += 64) {
        float e = eli + er2[cols_s[k]];
        ew[k] = (e >= 0.f) ? e : ALPHA * e;
    }
    __syncthreads();
    if (tid < 32) {
        float m = -1e30f;
        for (int k = tid; k < cnt; k += 32) m = fmaxf(m, ew[k]);
#pragma unroll
        for (int o = 16; o > 0; o >>= 1) m = fmaxf(m, __shfl_xor_sync(0xffffffffu, m, o));
        float s = 0.f;
        for (int k = tid; k < cnt; k += 32) { float v = __expf(ew[k] - m); ew[k] = v; s += v; }
#pragma unroll
        for (int o = 16; o > 0; o >>= 1) s += __shfl_xor_sync(0xffffffffu, s, o);
        float inv = 1.f / s;
        for (int k = tid; k < cnt; k += 32) ew[k] *= inv;
    }
    __syncthreads();
    int q = tid & 15, p = tid >> 4;
    const float4* Wh4 = (const float4*)Wh;
    float4 aa = make_float4(0.f, 0.f, 0.f, 0.f);
    float4 ab = make_float4(0.f, 0.f, 0.f, 0.f);
    int k = p;
    for (; k + 4 < cnt; k += 8) {
        float wa = ew[k];
        float4 va = Wh4[(size_t)cols_s[k] * 16 + q];
        float wb = ew[k + 4];
        float4 vb = Wh4[(size_t)cols_s[k + 4] * 16 + q];
        aa.x += wa * va.x; aa.y += wa * va.y; aa.z += wa * va.z; aa.w += wa * va.w;
        ab.x += wb * vb.x; ab.y += wb * vb.y; ab.z += wb * vb.z; ab.w += wb * vb.w;
    }
    if (k < cnt) {
        float wa = ew[k];
        float4 va = Wh4[(size_t)cols_s[k] * 16 + q];
        aa.x += wa * va.x; aa.y += wa * va.y; aa.z += wa * va.z; aa.w += wa * va.w;
    }
    aa.x += ab.x; aa.y += ab.y; aa.z += ab.z; aa.w += ab.w;
    red[tid] = aa;
    __syncthreads();
    if (tid < 16) {
        float4 a = red[tid], b = red[tid + 16], c = red[tid + 32], d = red[tid + 48];
        float4 s = make_float4(a.x + b.x + c.x + d.x, a.y + b.y + c.y + d.y,
                               a.z + b.z + c.z + d.z, a.w + b.w + c.w + d.w);
        s.x = (s.x > 0.f) ? s.x : (__expf(s.x) - 1.f);
        s.y = (s.y > 0.f) ? s.y : (__expf(s.y) - 1.f);
        s.z = (s.z > 0.f) ? s.z : (__expf(s.z) - 1.f);
        s.w = (s.w > 0.f) ? s.w : (__expf(s.w) - 1.f);
        ((float4*)gcs)[tid] = s;
    }
    __syncthreads();
    if (tid < 32) {           // t1 row = gc_row @ W1  [64 x 32]
        float a = 0.f;
#pragma unroll 16
        for (int kk = 0; kk < 64; kk++) a += gcs[kk] * W1[kk * 32 + tid];
        g_t1[i * 32 + tid] = a;
    }
}

// ---------------- h1 = relu(adj @ t1) fused with t23 = h1 @ [W2|W3] ----------
__global__ void k_spmm_t23(const float* __restrict__ W2, const float* __restrict__ W3) {
    __shared__ float Bs[32 * 32];
    int tid = threadIdx.x;
    for (int idx = tid; idx < 32 * 16; idx += 256) {
        int k = idx >> 4, c = idx & 15;
        Bs[k * 32 + c]      = W2[idx];
        Bs[k * 32 + 16 + c] = W3[idx];
    }
    __syncthreads();
    int r = blockIdx.x * 8 + (tid >> 5);
    int lane = tid & 31;
    int cnt = g_cnt[r];
    const int* cp = g_col + r * MAXNZ;
    float acc = 0.f;
    int k = 0;
    for (; k + 4 <= cnt; k += 4) {
        int j0 = cp[k], j1 = cp[k + 1], j2 = cp[k + 2], j3 = cp[k + 3];
        acc += g_t1[j0 * 32 + lane] + g_t1[j1 * 32 + lane]
             + g_t1[j2 * 32 + lane] + g_t1[j3 * 32 + lane];
    }
    for (; k < cnt; k++) acc += g_t1[cp[k] * 32 + lane];
    acc = fmaxf(acc, 0.f);
    float s = 0.f;
#pragma unroll
    for (int kk = 0; kk < 32; kk++) {
        float hk = __shfl_sync(0xffffffffu, acc, kk);
        s += hk * Bs[kk * 32 + lane];
    }
    g_t23[r * 32 + lane] = s;
}

// ---------------- mu/logvar spmm + reparameterize ----------------------------
__global__ void k_mlz(const float* __restrict__ eps, float* __restrict__ out) {
    int tid = threadIdx.x;
    int r = blockIdx.x * 8 + (tid >> 5);
    int lane = tid & 31;
    int cnt = g_cnt[r];
    const int* cp = g_col + r * MAXNZ;
    float acc = 0.f;
    int k = 0;
    for (; k + 4 <= cnt; k += 4) {
        int j0 = cp[k], j1 = cp[k + 1], j2 = cp[k + 2], j3 = cp[k + 3];
        acc += g_t23[j0 * 32 + lane] + g_t23[j1 * 32 + lane]
             + g_t23[j2 * 32 + lane] + g_t23[j3 * 32 + lane];
    }
    for (; k < cnt; k++) acc += g_t23[cp[k] * 32 + lane];
    float other = __shfl_xor_sync(0xffffffffu, acc, 16);
    const size_t NN = (size_t)NV * NV;
    if (lane < 16) {
        float mu = acc, lv = other;
        float z = eps[r * 16 + lane] * expf(lv) + mu;
        g_z[r * 16 + lane] = z;
        out[NN + (size_t)r * 16 + lane] = mu;
    } else {
        out[NN + (size_t)NV * 16 + (size_t)r * 16 + (lane - 16)] = acc;
    }
}

// ---------------- adj_rec = z @ z^T : 128x128 tile, 8x8 micro, f32x2 ---------
__global__ __launch_bounds__(256) void k_zz(float* __restrict__ out) {
    int m0 = blockIdx.y * 128, n0 = blockIdx.x * 128;
    __shared__ float zr[16][128];
    __shared__ float zc[16][128];
    int tid = threadIdx.x;
    const float4* z4 = (const float4*)g_z;
#pragma unroll
    for (int t = tid; t < 512; t += 256) {
        int r = t >> 2, c4 = (t & 3) * 4;
        float4 v = z4[(size_t)(m0 + r) * 4 + (t & 3)];
        zr[c4][r] = v.x; zr[c4 + 1][r] = v.y; zr[c4 + 2][r] = v.z; zr[c4 + 3][r] = v.w;
        float4 w = z4[(size_t)(n0 + r) * 4 + (t & 3)];
        zc[c4][r] = w.x; zc[c4 + 1][r] = w.y; zc[c4 + 2][r] = w.z; zc[c4 + 3][r] = w.w;
    }
    __syncthreads();
    int tx = tid & 15, ty = tid >> 4;
    unsigned long long acc2[8][4] = {};
#pragma unroll
    for (int kk = 0; kk < 16; kk++) {
        float4 b0 = *(float4*)&zc[kk][tx * 8];
        float4 b1 = *(float4*)&zc[kk][tx * 8 + 4];
        unsigned long long pb0 = pack2(b0.x, b0.y), pb1 = pack2(b0.z, b0.w);
        unsigned long long pb2 = pack2(b1.x, b1.y), pb3 = pack2(b1.z, b1.w);
        float4 a0 = *(float4*)&zr[kk][ty * 8];
        float4 a1 = *(float4*)&zr[kk][ty * 8 + 4];
        float av[8] = {a0.x, a0.y, a0.z, a0.w, a1.x, a1.y, a1.z, a1.w};
#pragma unroll
        for (int i = 0; i < 8; i++) {
            unsigned long long ai = pack2(av[i], av[i]);
            ffma2(acc2[i][0], ai, pb0);
            ffma2(acc2[i][1], ai, pb1);
            ffma2(acc2[i][2], ai, pb2);
            ffma2(acc2[i][3], ai, pb3);
        }
    }
#pragma unroll
    for (int i = 0; i < 8; i++) {
        float2 c0 = unpack2(acc2[i][0]), c1 = unpack2(acc2[i][1]);
        float2 c2 = unpack2(acc2[i][2]), c3 = unpack2(acc2[i][3]);
        float* op = out + (size_t)(m0 + ty * 8 + i) * NV + n0 + tx * 8;
        *(float4*)op       = make_float4(c0.x, c0.y, c1.x, c1.y);
        *(float4*)(op + 4) = make_float4(c2.x, c2.y, c3.x, c3.y);
    }
}

// ---------------- launch ------------------------------------------------------
extern "C" void kernel_launch(void* const* d_in, const int* in_sizes, int n_in,
                              void* d_out, int out_size) {
    const float* x       = (const float*)d_in[0];
    const float* adj     = (const float*)d_in[1];
    const float* W_heads = (const float*)d_in[2];
    const float* a_heads = (const float*)d_in[3];
    const float* W_att   = (const float*)d_in[4];
    const float* a_att   = (const float*)d_in[5];
    const float* W1      = (const float*)d_in[6];
    const float* W2      = (const float*)d_in[7];
    const float* W3      = (const float*)d_in[8];
    const float* eps     = (const float*)d_in[9];
    float* out = (float*)d_out;

    float *p_Whcat, *p_cat, *p_Whc, *p_el, *p_er, *p_el2, *p_er2;
    cudaGetSymbolAddress((void**)&p_Whcat, g_Whcat);
    cudaGetSymbolAddress((void**)&p_cat,   g_cat);
    cudaGetSymbolAddress((void**)&p_Whc,   g_Whc);
    cudaGetSymbolAddress((void**)&p_el,    g_el);
    cudaGetSymbolAddress((void**)&p_er,    g_er);
    cudaGetSymbolAddress((void**)&p_el2,   g_el2);
    cudaGetSymbolAddress((void**)&p_er2,   g_er2);

    // one-time aux stream + events (host-side only; created outside capture)
    static cudaStream_t s_aux = nullptr;
    static cudaEvent_t ev_fork = nullptr, ev_join = nullptr;
    if (!s_aux) {
        cudaStreamCreateWithFlags(&s_aux, cudaStreamNonBlocking);
        cudaEventCreateWithFlags(&ev_fork, cudaEventDisableTiming);
        cudaEventCreateWithFlags(&ev_join, cudaEventDisableTiming);
    }

    // fork: CSR (DRAM-bound) overlaps heads-GEMM (compute-bound)
    cudaEventRecord(ev_fork, 0);
    cudaStreamWaitEvent(s_aux, ev_fork, 0);
    k_csr<<<NV / 8, 256, 0, s_aux>>>(adj);
    cudaEventRecord(ev_join, s_aux);

    // Wh for all heads + fused el/er
    k_gemm<<<dim3(NV / 64, HV), 128>>>(x, W_heads, p_Whcat, DV, HF, DV * F1V, F1V,
                                       a_heads, 2 * F1V, p_el, p_er, HV);
    cudaStreamWaitEvent(0, ev_join, 0);

    // multi-head GAT aggregate -> cat
    k_gat4<<<NV, 256>>>(p_Whcat, p_el, p_er, p_cat);
    // Whc = cat @ W_att + fused el2/er2
    k_gemm<<<dim3(NV / 64, 1), 128>>>(p_cat, W_att, p_Whc, HF, F1V, 0, 0,
                                      a_att, 0, p_el2, p_er2, 1);
    // attention-level GAT + fused t1
    k_gat1<<<NV, 64>>>(p_Whc, p_el2, p_er2, W1);
    // h1 = relu(adj@t1) + fused t23
    k_spmm_t23<<<NV / 8, 256>>>(W2, W3);
    // mu/logvar spmm + reparameterize
    k_mlz<<<NV / 8, 256>>>(eps, out);
    // adj_rec = z @ z^T
    k_zz<<<dim3(NV / 128, NV / 128), 256>>>(out);
}

// round 6
// speedup vs baseline: 1.4265x; 1.4265x over previous
#include <cuda_runtime.h>
#include <cstdint>

#define NV   4096
#define DV   512
#define F1V  64
#define HV   4
#define HF   256   // H*F1
#define MAXNZ 128
#define ALPHA 0.2f

// ---------------- scratch (device globals; no allocs allowed) ----------------
__device__ int   g_col[NV * MAXNZ];
__device__ int   g_cnt[NV];
__device__ float g_Whcat[NV * HF];   // x @ W_heads (head h in cols [h*64,(h+1)*64))
__device__ float g_cat[NV * HF];     // multi-head GAT output (elu'd, concat)
__device__ float g_Whc[NV * F1V];    // cat @ W_att
__device__ float g_el[NV * HV];      // [i][h] float4-friendly
__device__ float g_er[NV * HV];
__device__ float g_el2[NV];
__device__ float g_er2[NV];
__device__ float g_t1[NV * 32];
__device__ float g_t23[NV * 32];     // [mu-pre | logvar-pre] per row (16+16)
__device__ float g_z[NV * 16];

// ---------------- f32x2 packed-FMA helpers (ptxas won't auto-fuse) -----------
__device__ __forceinline__ unsigned long long pack2(float lo, float hi) {
    unsigned long long r;
    asm("mov.b64 %0, {%1, %2};" : "=l"(r) : "f"(lo), "f"(hi));
    return r;
}
__device__ __forceinline__ void ffma2(unsigned long long& d, unsigned long long a,
                                      unsigned long long b) {
    asm("fma.rn.f32x2 %0, %1, %2, %0;" : "+l"(d) : "l"(a), "l"(b));
}
__device__ __forceinline__ float2 unpack2(unsigned long long v) {
    float2 f;
    asm("mov.b64 {%0, %1}, %2;" : "=f"(f.x), "=f"(f.y) : "l"(v));
    return f;
}

// ---------------- CSR build: warp per row, float4 stream ---------------------
__global__ void k_csr(const float* __restrict__ adj) {
    int wid = threadIdx.x >> 5, lane = threadIdx.x & 31;
    int row = blockIdx.x * 8 + wid;
    const float4* r4 = (const float4*)(adj + (size_t)row * NV);
    unsigned lm = (1u << lane) - 1u;
    int base = 0;
    int* cp = g_col + row * MAXNZ;
#pragma unroll 4
    for (int c0 = 0; c0 < NV / 4; c0 += 32) {
        float4 v = r4[c0 + lane];
        unsigned b0 = __ballot_sync(0xffffffffu, v.x > 0.f);
        unsigned b1 = __ballot_sync(0xffffffffu, v.y > 0.f);
        unsigned b2 = __ballot_sync(0xffffffffu, v.z > 0.f);
        unsigned b3 = __ballot_sync(0xffffffffu, v.w > 0.f);
        int t0 = __popc(b0), t1 = __popc(b1), t2 = __popc(b2), t3 = __popc(b3);
        int col = (c0 + lane) * 4;
        if (v.x > 0.f) { int p = base + __popc(b0 & lm);                if (p < MAXNZ) cp[p] = col; }
        if (v.y > 0.f) { int p = base + t0 + __popc(b1 & lm);           if (p < MAXNZ) cp[p] = col + 1; }
        if (v.z > 0.f) { int p = base + t0 + t1 + __popc(b2 & lm);      if (p < MAXNZ) cp[p] = col + 2; }
        if (v.w > 0.f) { int p = base + t0 + t1 + t2 + __popc(b3 & lm); if (p < MAXNZ) cp[p] = col + 3; }
        base += t0 + t1 + t2 + t3;
    }
    if (lane == 0) g_cnt[row] = (base < MAXNZ) ? base : MAXNZ;
}

// ---------------- GEMM: BM=RM*8 x 64 tile, 128 thr, micro RMx4, f32x2 --------
// C[m0:m0+BM, coff:+64] = A[M,K] @ B[K,64] ; fused el/er = C_tile @ a[:64]/a[64:]
template <int RM>
__global__ __launch_bounds__(128) void k_gemm(const float* __restrict__ A,
                                              const float* __restrict__ Bbase,
                                              float* __restrict__ Cbase,
                                              int K, int ldc, int bstride, int ccoloff,
                                              const float* __restrict__ avec, int avstride,
                                              float* __restrict__ el_out,
                                              float* __restrict__ er_out, int estr) {
    const int BM = RM * 8;
    int h = blockIdx.y;
    const float* B = Bbase + (size_t)h * bstride;
    int m0 = blockIdx.x * BM;
    int tid = threadIdx.x;
    int tx = tid & 15, ty = tid >> 4;
    __shared__ float As[16][BM];
    __shared__ float Bs[16][64];
    unsigned long long acc2[RM][2] = {};
    for (int k0 = 0; k0 < K; k0 += 16) {
#pragma unroll
        for (int t = tid; t < BM * 4; t += 128) {   // A tile BMx16 -> transposed
            int r = t >> 2, c4 = (t & 3) * 4;
            float4 v = *(const float4*)(A + (size_t)(m0 + r) * K + k0 + c4);
            As[c4][r] = v.x; As[c4 + 1][r] = v.y; As[c4 + 2][r] = v.z; As[c4 + 3][r] = v.w;
        }
#pragma unroll
        for (int t = tid; t < 256; t += 128) {      // B tile 16x64
            int r = t >> 4, c = (t & 15) * 4;
            *(float4*)&Bs[r][c] = *(const float4*)(B + (size_t)(k0 + r) * 64 + c);
        }
        __syncthreads();
#pragma unroll
        for (int kk = 0; kk < 16; kk++) {
            float4 b = *(float4*)&Bs[kk][tx * 4];
            unsigned long long b01 = pack2(b.x, b.y), b23 = pack2(b.z, b.w);
            float av[RM];
            if constexpr (RM == 4) {
                float4 a = *(float4*)&As[kk][ty * 4];
                av[0] = a.x; av[1] = a.y; av[2] = a.z; av[3] = a.w;
            } else {
                float2 a = *(float2*)&As[kk][ty * 2];
                av[0] = a.x; av[1] = a.y;
            }
#pragma unroll
            for (int i = 0; i < RM; i++) {
                unsigned long long ai = pack2(av[i], av[i]);
                ffma2(acc2[i][0], ai, b01);
                ffma2(acc2[i][1], ai, b23);
            }
        }
        __syncthreads();
    }
    int coff = h * ccoloff;
    float4 aL = *(const float4*)(avec + (size_t)h * avstride + tx * 4);
    float4 aR = *(const float4*)(avec + (size_t)h * avstride + 64 + tx * 4);
#pragma unroll
    for (int i = 0; i < RM; i++) {
        float2 c0 = unpack2(acc2[i][0]), c1 = unpack2(acc2[i][1]);
        *(float4*)(Cbase + (size_t)(m0 + ty * RM + i) * ldc + coff + tx * 4)
            = make_float4(c0.x, c0.y, c1.x, c1.y);
        float sl = c0.x * aL.x + c0.y * aL.y + c1.x * aL.z + c1.y * aL.w;
        float sr = c0.x * aR.x + c0.y * aR.y + c1.x * aR.z + c1.y * aR.w;
#pragma unroll
        for (int o = 8; o > 0; o >>= 1) {
            sl += __shfl_xor_sync(0xffffffffu, sl, o);
            sr += __shfl_xor_sync(0xffffffffu, sr, o);
        }
        if (tx == 0) {
            int row = m0 + ty * RM + i;
            el_out[row * estr + h] = sl;
            er_out[row * estr + h] = sr;
        }
    }
}

// ---------------- 4-head GAT: softmax over neighbors + aggregate + elu -------
__global__ __launch_bounds__(256) void k_gat4(const float* __restrict__ Wh,
                                              const float* __restrict__ el4p,
                                              const float* __restrict__ er4p,
                                              float* __restrict__ out) {
    int i = blockIdx.x;
    __shared__ int cols_s[MAXNZ];
    __shared__ float ew[4][MAXNZ];
    __shared__ float4 red[256];
    int cnt = g_cnt[i];
    int tid = threadIdx.x;
    float4 eli = ((const float4*)el4p)[i];
    for (int k = tid; k < cnt; k += 256) cols_s[k] = g_col[i * MAXNZ + k];
    __syncthreads();
    for (int k = tid; k < cnt; k += 256) {
        float4 er4 = ((const float4*)er4p)[cols_s[k]];
        float e0 = eli.x + er4.x, e1 = eli.y + er4.y, e2 = eli.z + er4.z, e3 = eli.w + er4.w;
        ew[0][k] = (e0 >= 0.f) ? e0 : ALPHA * e0;
        ew[1][k] = (e1 >= 0.f) ? e1 : ALPHA * e1;
        ew[2][k] = (e2 >= 0.f) ? e2 : ALPHA * e2;
        ew[3][k] = (e3 >= 0.f) ? e3 : ALPHA * e3;
    }
    __syncthreads();
    int wid = tid >> 5, lane = tid & 31;
    if (wid < 4) {
        float m = -1e30f;
        for (int k = lane; k < cnt; k += 32) m = fmaxf(m, ew[wid][k]);
#pragma unroll
        for (int o = 16; o > 0; o >>= 1) m = fmaxf(m, __shfl_xor_sync(0xffffffffu, m, o));
        float s = 0.f;
        for (int k = lane; k < cnt; k += 32) {
            float v = __expf(ew[wid][k] - m);
            ew[wid][k] = v; s += v;
        }
#pragma unroll
        for (int o = 16; o > 0; o >>= 1) s += __shfl_xor_sync(0xffffffffu, s, o);
        float inv = 1.f / s;
        for (int k = lane; k < cnt; k += 32) ew[wid][k] *= inv;
    }
    __syncthreads();
    int q = tid & 63;          // float4 column
    int p = tid >> 6;          // phase 0..3
    int h = q >> 4;
    const float4* Wh4 = (const float4*)Wh;
    float4 aa = make_float4(0.f, 0.f, 0.f, 0.f);
    float4 ab = make_float4(0.f, 0.f, 0.f, 0.f);
    int k = p;
    for (; k + 4 < cnt; k += 8) {
        float wa = ew[h][k];
        float4 va = Wh4[(size_t)cols_s[k] * 64 + q];
        float wb = ew[h][k + 4];
        float4 vb = Wh4[(size_t)cols_s[k + 4] * 64 + q];
        aa.x += wa * va.x; aa.y += wa * va.y; aa.z += wa * va.z; aa.w += wa * va.w;
        ab.x += wb * vb.x; ab.y += wb * vb.y; ab.z += wb * vb.z; ab.w += wb * vb.w;
    }
    if (k < cnt) {
        float wa = ew[h][k];
        float4 va = Wh4[(size_t)cols_s[k] * 64 + q];
        aa.x += wa * va.x; aa.y += wa * va.y; aa.z += wa * va.z; aa.w += wa * va.w;
    }
    aa.x += ab.x; aa.y += ab.y; aa.z += ab.z; aa.w += ab.w;
    red[tid] = aa;
    __syncthreads();
    if (tid < 64) {
        float4 a = red[tid], b = red[tid + 64], c = red[tid + 128], d = red[tid + 192];
        float4 s = make_float4(a.x + b.x + c.x + d.x, a.y + b.y + c.y + d.y,
                               a.z + b.z + c.z + d.z, a.w + b.w + c.w + d.w);
        s.x = (s.x > 0.f) ? s.x : (__expf(s.x) - 1.f);
        s.y = (s.y > 0.f) ? s.y : (__expf(s.y) - 1.f);
        s.z = (s.z > 0.f) ? s.z : (__expf(s.z) - 1.f);
        s.w = (s.w > 0.f) ? s.w : (__expf(s.w) - 1.f);
        ((float4*)out)[(size_t)i * 64 + tid] = s;
    }
}

// ---------------- att GAT (1 head) fused with t1 = gc @ W1 -------------------
__global__ __launch_bounds__(64) void k_gat1(const float* __restrict__ Wh,
                                             const float* __restrict__ el2,
                                             const float* __restrict__ er2,
                                             const float* __restrict__ W1) {
    int i = blockIdx.x;
    __shared__ int cols_s[MAXNZ];
    __shared__ float ew[MAXNZ];
    __shared__ float4 red[64];
    __shared__ float gcs[64];
    int cnt = g_cnt[i];
    int tid = threadIdx.x;
    float eli = el2[i];
    for (int k = tid; k < cnt; k += 64) cols_s[k] = g_col[i * MAXNZ + k];
    __syncthreads();
    for (int k = tid; k < cnt; k += 64) {
        float e = eli + er2[cols_s[k]];
        ew[k] = (e >= 0.f) ? e : ALPHA * e;
    }
    __syncthreads();
    if (tid < 32) {
        float m = -1e30f;
        for (int k = tid; k < cnt; k += 32) m = fmaxf(m, ew[k]);
#pragma unroll
        for (int o = 16; o > 0; o >>= 1) m = fmaxf(m, __shfl_xor_sync(0xffffffffu, m, o));
        float s = 0.f;
        for (int k = tid; k < cnt; k += 32) { float v = __expf(ew[k] - m); ew[k] = v; s += v; }
#pragma unroll
        for (int o = 16; o > 0; o >>= 1) s += __shfl_xor_sync(0xffffffffu, s, o);
        float inv = 1.f / s;
        for (int k = tid; k < cnt; k += 32) ew[k] *= inv;
    }
    __syncthreads();
    int q = tid & 15, p = tid >> 4;
    const float4* Wh4 = (const float4*)Wh;
    float4 aa = make_float4(0.f, 0.f, 0.f, 0.f);
    float4 ab = make_float4(0.f, 0.f, 0.f, 0.f);
    int k = p;
    for (; k + 4 < cnt; k += 8) {
        float wa = ew[k];
        float4 va = Wh4[(size_t)cols_s[k] * 16 + q];
        float wb = ew[k + 4];
        float4 vb = Wh4[(size_t)cols_s[k + 4] * 16 + q];
        aa.x += wa * va.x; aa.y += wa * va.y; aa.z += wa * va.z; aa.w += wa * va.w;
        ab.x += wb * vb.x; ab.y += wb * vb.y; ab.z += wb * vb.z; ab.w += wb * vb.w;
    }
    if (k < cnt) {
        float wa = ew[k];
        float4 va = Wh4[(size_t)cols_s[k] * 16 + q];
        aa.x += wa * va.x; aa.y += wa * va.y; aa.z += wa * va.z; aa.w += wa * va.w;
    }
    aa.x += ab.x; aa.y += ab.y; aa.z += ab.z; aa.w += ab.w;
    red[tid] = aa;
    __syncthreads();
    if (tid < 16) {
        float4 a = red[tid], b = red[tid + 16], c = red[tid + 32], d = red[tid + 48];
        float4 s = make_float4(a.x + b.x + c.x + d.x, a.y + b.y + c.y + d.y,
                               a.z + b.z + c.z + d.z, a.w + b.w + c.w + d.w);
        s.x = (s.x > 0.f) ? s.x : (__expf(s.x) - 1.f);
        s.y = (s.y > 0.f) ? s.y : (__expf(s.y) - 1.f);
        s.z = (s.z > 0.f) ? s.z : (__expf(s.z) - 1.f);
        s.w = (s.w > 0.f) ? s.w : (__expf(s.w) - 1.f);
        ((float4*)gcs)[tid] = s;
    }
    __syncthreads();
    if (tid < 32) {           // t1 row = gc_row @ W1  [64 x 32]
        float a = 0.f;
#pragma unroll 16
        for (int kk = 0; kk < 64; kk++) a += gcs[kk] * W1[kk * 32 + tid];
        g_t1[i * 32 + tid] = a;
    }
}

// ---------------- h1 = relu(adj @ t1) fused with t23 = h1 @ [W2|W3] ----------
__global__ void k_spmm_t23(const float* __restrict__ W2, const float* __restrict__ W3) {
    __shared__ float Bs[32 * 32];
    int tid = threadIdx.x;
    for (int idx = tid; idx < 32 * 16; idx += 256) {
        int k = idx >> 4, c = idx & 15;
        Bs[k * 32 + c]      = W2[idx];
        Bs[k * 32 + 16 + c] = W3[idx];
    }
    __syncthreads();
    int r = blockIdx.x * 8 + (tid >> 5);
    int lane = tid & 31;
    int cnt = g_cnt[r];
    const int* cp = g_col + r * MAXNZ;
    float acc = 0.f;
    int k = 0;
    for (; k + 4 <= cnt; k += 4) {
        int j0 = cp[k], j1 = cp[k + 1], j2 = cp[k + 2], j3 = cp[k + 3];
        acc += g_t1[j0 * 32 + lane] + g_t1[j1 * 32 + lane]
             + g_t1[j2 * 32 + lane] + g_t1[j3 * 32 + lane];
    }
    for (; k < cnt; k++) acc += g_t1[cp[k] * 32 + lane];
    acc = fmaxf(acc, 0.f);
    float s = 0.f;
#pragma unroll
    for (int kk = 0; kk < 32; kk++) {
        float hk = __shfl_sync(0xffffffffu, acc, kk);
        s += hk * Bs[kk * 32 + lane];
    }
    g_t23[r * 32 + lane] = s;
}

// ---------------- mu/logvar spmm + reparameterize ----------------------------
__global__ void k_mlz(const float* __restrict__ eps, float* __restrict__ out) {
    int tid = threadIdx.x;
    int r = blockIdx.x * 8 + (tid >> 5);
    int lane = tid & 31;
    int cnt = g_cnt[r];
    const int* cp = g_col + r * MAXNZ;
    float acc = 0.f;
    int k = 0;
    for (; k + 4 <= cnt; k += 4) {
        int j0 = cp[k], j1 = cp[k + 1], j2 = cp[k + 2], j3 = cp[k + 3];
        acc += g_t23[j0 * 32 + lane] + g_t23[j1 * 32 + lane]
             + g_t23[j2 * 32 + lane] + g_t23[j3 * 32 + lane];
    }
    for (; k < cnt; k++) acc += g_t23[cp[k] * 32 + lane];
    float other = __shfl_xor_sync(0xffffffffu, acc, 16);
    const size_t NN = (size_t)NV * NV;
    if (lane < 16) {
        float mu = acc, lv = other;
        float z = eps[r * 16 + lane] * expf(lv) + mu;
        g_z[r * 16 + lane] = z;
        out[NN + (size_t)r * 16 + lane] = mu;
    } else {
        out[NN + (size_t)NV * 16 + (size_t)r * 16 + (lane - 16)] = acc;
    }
}

// ---------------- adj_rec = z @ z^T : 128x128 tile, 8x8 micro, f32x2 ---------
__global__ __launch_bounds__(256) void k_zz(float* __restrict__ out) {
    int m0 = blockIdx.y * 128, n0 = blockIdx.x * 128;
    __shared__ float zr[16][128];
    __shared__ float zc[16][128];
    int tid = threadIdx.x;
    const float4* z4 = (const float4*)g_z;
#pragma unroll
    for (int t = tid; t < 512; t += 256) {
        int r = t >> 2, c4 = (t & 3) * 4;
        float4 v = z4[(size_t)(m0 + r) * 4 + (t & 3)];
        zr[c4][r] = v.x; zr[c4 + 1][r] = v.y; zr[c4 + 2][r] = v.z; zr[c4 + 3][r] = v.w;
        float4 w = z4[(size_t)(n0 + r) * 4 + (t & 3)];
        zc[c4][r] = w.x; zc[c4 + 1][r] = w.y; zc[c4 + 2][r] = w.z; zc[c4 + 3][r] = w.w;
    }
    __syncthreads();
    int tx = tid & 15, ty = tid >> 4;
    unsigned long long acc2[8][4] = {};
#pragma unroll
    for (int kk = 0; kk < 16; kk++) {
        float4 b0 = *(float4*)&zc[kk][tx * 8];
        float4 b1 = *(float4*)&zc[kk][tx * 8 + 4];
        unsigned long long pb0 = pack2(b0.x, b0.y), pb1 = pack2(b0.z, b0.w);
        unsigned long long pb2 = pack2(b1.x, b1.y), pb3 = pack2(b1.z, b1.w);
        float4 a0 = *(float4*)&zr[kk][ty * 8];
        float4 a1 = *(float4*)&zr[kk][ty * 8 + 4];
        float av[8] = {a0.x, a0.y, a0.z, a0.w, a1.x, a1.y, a1.z, a1.w};
#pragma unroll
        for (int i = 0; i < 8; i++) {
            unsigned long long ai = pack2(av[i], av[i]);
            ffma2(acc2[i][0], ai, pb0);
            ffma2(acc2[i][1], ai, pb1);
            ffma2(acc2[i][2], ai, pb2);
            ffma2(acc2[i][3], ai, pb3);
        }
    }
#pragma unroll
    for (int i = 0; i < 8; i++) {
        float2 c0 = unpack2(acc2[i][0]), c1 = unpack2(acc2[i][1]);
        float2 c2 = unpack2(acc2[i][2]), c3 = unpack2(acc2[i][3]);
        float* op = out + (size_t)(m0 + ty * 8 + i) * NV + n0 + tx * 8;
        *(float4*)op       = make_float4(c0.x, c0.y, c1.x, c1.y);
        *(float4*)(op + 4) = make_float4(c2.x, c2.y, c3.x, c3.y);
    }
}

// ---------------- launch (single stream, no fork/join) ------------------------
extern "C" void kernel_launch(void* const* d_in, const int* in_sizes, int n_in,
                              void* d_out, int out_size) {
    const float* x       = (const float*)d_in[0];
    const float* adj     = (const float*)d_in[1];
    const float* W_heads = (const float*)d_in[2];
    const float* a_heads = (const float*)d_in[3];
    const float* W_att   = (const float*)d_in[4];
    const float* a_att   = (const float*)d_in[5];
    const float* W1      = (const float*)d_in[6];
    const float* W2      = (const float*)d_in[7];
    const float* W3      = (const float*)d_in[8];
    const float* eps     = (const float*)d_in[9];
    float* out = (float*)d_out;

    float *p_Whcat, *p_cat, *p_Whc, *p_el, *p_er, *p_el2, *p_er2;
    cudaGetSymbolAddress((void**)&p_Whcat, g_Whcat);
    cudaGetSymbolAddress((void**)&p_cat,   g_cat);
    cudaGetSymbolAddress((void**)&p_Whc,   g_Whc);
    cudaGetSymbolAddress((void**)&p_el,    g_el);
    cudaGetSymbolAddress((void**)&p_er,    g_er);
    cudaGetSymbolAddress((void**)&p_el2,   g_el2);
    cudaGetSymbolAddress((void**)&p_er2,   g_er2);

    // 1. CSR of adj
    k_csr<<<NV / 8, 256>>>(adj);
    // 2. Wh for all heads + fused el/er  (BM=32 -> 512 blocks)
    k_gemm<4><<<dim3(NV / 32, HV), 128>>>(x, W_heads, p_Whcat, DV, HF, DV * F1V, F1V,
                                          a_heads, 2 * F1V, p_el, p_er, HV);
    // 3. multi-head GAT aggregate -> cat
    k_gat4<<<NV, 256>>>(p_Whcat, p_el, p_er, p_cat);
    // 4. Whc = cat @ W_att + fused el2/er2  (BM=16 -> 256 blocks)
    k_gemm<2><<<dim3(NV / 16, 1), 128>>>(p_cat, W_att, p_Whc, HF, F1V, 0, 0,
                                         a_att, 0, p_el2, p_er2, 1);
    // 5. attention-level GAT + fused t1
    k_gat1<<<NV, 64>>>(p_Whc, p_el2, p_er2, W1);
    // 6. h1 = relu(adj@t1) + fused t23
    k_spmm_t23<<<NV / 8, 256>>>(W2, W3);
    // 7. mu/logvar spmm + reparameterize
    k_mlz<<<NV / 8, 256>>>(eps, out);
    // 8. adj_rec = z @ z^T
    k_zz<<<dim3(NV / 128, NV / 128), 256>>>(out);
}

// round 9
// speedup vs baseline: 1.4313x; 1.0033x over previous
#include <cuda_runtime.h>
#include <cstdint>

#define NV   4096
#define DV   512
#define F1V  64
#define HV   4
#define HF   256   // H*F1
#define MAXNZ 128
#define ALPHA 0.2f

// ---------------- scratch (device globals; no allocs allowed) ----------------
__device__ int   g_col[NV * MAXNZ];
__device__ int   g_cnt[NV];
__device__ float g_Whcat[NV * HF];   // x @ W_heads (head h in cols [h*64,(h+1)*64))
__device__ float g_cat[NV * HF];     // multi-head GAT output (elu'd, concat)
__device__ float g_Whc[NV * F1V];    // cat @ W_att
__device__ float g_el[NV * HV];      // [i][h]
__device__ float g_er[NV * HV];
__device__ float g_el2[NV];
__device__ float g_er2[NV];
__device__ float g_t1[NV * 32];
__device__ float g_t23[NV * 32];     // [mu-pre | logvar-pre] per row (16+16)
__device__ float g_z[NV * 16];

// ---------------- f32x2 packed-FMA helpers (ptxas won't auto-fuse) -----------
__device__ __forceinline__ unsigned long long pack2(float lo, float hi) {
    unsigned long long r;
    asm("mov.b64 %0, {%1, %2};" : "=l"(r) : "f"(lo), "f"(hi));
    return r;
}
__device__ __forceinline__ void ffma2(unsigned long long& d, unsigned long long a,
                                      unsigned long long b) {
    asm("fma.rn.f32x2 %0, %1, %2, %0;" : "+l"(d) : "l"(a), "l"(b));
}
__device__ __forceinline__ float2 unpack2(unsigned long long v) {
    float2 f;
    asm("mov.b64 {%0, %1}, %2;" : "=f"(f.x), "=f"(f.y) : "l"(v));
    return f;
}

// ---------------- CSR build: warp per row, float4 stream ---------------------
__global__ void k_csr(const float* __restrict__ adj) {
    int wid = threadIdx.x >> 5, lane = threadIdx.x & 31;
    int row = blockIdx.x * 8 + wid;
    const float4* r4 = (const float4*)(adj + (size_t)row * NV);
    unsigned lm = (1u << lane) - 1u;
    int base = 0;
    int* cp = g_col + row * MAXNZ;
#pragma unroll 4
    for (int c0 = 0; c0 < NV / 4; c0 += 32) {
        float4 v = r4[c0 + lane];
        unsigned b0 = __ballot_sync(0xffffffffu, v.x > 0.f);
        unsigned b1 = __ballot_sync(0xffffffffu, v.y > 0.f);
        unsigned b2 = __ballot_sync(0xffffffffu, v.z > 0.f);
        unsigned b3 = __ballot_sync(0xffffffffu, v.w > 0.f);
        int t0 = __popc(b0), t1 = __popc(b1), t2 = __popc(b2), t3 = __popc(b3);
        int col = (c0 + lane) * 4;
        if (v.x > 0.f) { int p = base + __popc(b0 & lm);                if (p < MAXNZ) cp[p] = col; }
        if (v.y > 0.f) { int p = base + t0 + __popc(b1 & lm);           if (p < MAXNZ) cp[p] = col + 1; }
        if (v.z > 0.f) { int p = base + t0 + t1 + __popc(b2 & lm);      if (p < MAXNZ) cp[p] = col + 2; }
        if (v.w > 0.f) { int p = base + t0 + t1 + t2 + __popc(b3 & lm); if (p < MAXNZ) cp[p] = col + 3; }
        base += t0 + t1 + t2 + t3;
    }
    if (lane == 0) g_cnt[row] = (base < MAXNZ) ? base : MAXNZ;
}

// ---------------- GEMM: BM=RM*8 x 64 tile, 128 thr, micro RMx4, f32x2 --------
// C[m0:m0+BM, coff:+64] = A[M,K] @ B[K,64] ; fused el/er = C_tile @ a[:64]/a[64:]
template <int RM>
__global__ __launch_bounds__(128) void k_gemm(const float* __restrict__ A,
                                              const float* __restrict__ Bbase,
                                              float* __restrict__ Cbase,
                                              int K, int ldc, int bstride, int ccoloff,
                                              const float* __restrict__ avec, int avstride,
                                              float* __restrict__ el_out,
                                              float* __restrict__ er_out, int estr) {
    const int BM = RM * 8;
    int h = blockIdx.y;
    const float* B = Bbase + (size_t)h * bstride;
    int m0 = blockIdx.x * BM;
    int tid = threadIdx.x;
    int tx = tid & 15, ty = tid >> 4;
    __shared__ float As[16][BM];
    __shared__ float Bs[16][64];
    unsigned long long acc2[RM][2] = {};
    for (int k0 = 0; k0 < K; k0 += 16) {
#pragma unroll
        for (int t = tid; t < BM * 4; t += 128) {   // A tile BMx16 -> transposed
            int r = t >> 2, c4 = (t & 3) * 4;
            float4 v = *(const float4*)(A + (size_t)(m0 + r) * K + k0 + c4);
            As[c4][r] = v.x; As[c4 + 1][r] = v.y; As[c4 + 2][r] = v.z; As[c4 + 3][r] = v.w;
        }
#pragma unroll
        for (int t = tid; t < 256; t += 128) {      // B tile 16x64
            int r = t >> 4, c = (t & 15) * 4;
            *(float4*)&Bs[r][c] = *(const float4*)(B + (size_t)(k0 + r) * 64 + c);
        }
        __syncthreads();
#pragma unroll
        for (int kk = 0; kk < 16; kk++) {
            float4 b = *(float4*)&Bs[kk][tx * 4];
            unsigned long long b01 = pack2(b.x, b.y), b23 = pack2(b.z, b.w);
            float av[RM];
            if constexpr (RM == 4) {
                float4 a = *(float4*)&As[kk][ty * 4];
                av[0] = a.x; av[1] = a.y; av[2] = a.z; av[3] = a.w;
            } else if constexpr (RM == 2) {
                float2 a = *(float2*)&As[kk][ty * 2];
                av[0] = a.x; av[1] = a.y;
            } else {
                av[0] = As[kk][ty];
            }
#pragma unroll
            for (int i = 0; i < RM; i++) {
                unsigned long long ai = pack2(av[i], av[i]);
                ffma2(acc2[i][0], ai, b01);
                ffma2(acc2[i][1], ai, b23);
            }
        }
        __syncthreads();
    }
    int coff = h * ccoloff;
    float4 aL = *(const float4*)(avec + (size_t)h * avstride + tx * 4);
    float4 aR = *(const float4*)(avec + (size_t)h * avstride + 64 + tx * 4);
#pragma unroll
    for (int i = 0; i < RM; i++) {
        float2 c0 = unpack2(acc2[i][0]), c1 = unpack2(acc2[i][1]);
        *(float4*)(Cbase + (size_t)(m0 + ty * RM + i) * ldc + coff + tx * 4)
            = make_float4(c0.x, c0.y, c1.x, c1.y);
        float sl = c0.x * aL.x + c0.y * aL.y + c1.x * aL.z + c1.y * aL.w;
        float sr = c0.x * aR.x + c0.y * aR.y + c1.x * aR.z + c1.y * aR.w;
#pragma unroll
        for (int o = 8; o > 0; o >>= 1) {
            sl += __shfl_xor_sync(0xffffffffu, sl, o);
            sr += __shfl_xor_sync(0xffffffffu, sr, o);
        }
        if (tx == 0) {
            int row = m0 + ty * RM + i;
            el_out[row * estr + h] = sl;
            er_out[row * estr + h] = sr;
        }
    }
}

// ---------------- 4-head GAT: warp per (row, head), no block syncs -----------
__global__ __launch_bounds__(256) void k_gat4w(const float* __restrict__ Wh,
                                               const float* __restrict__ el,
                                               const float* __restrict__ er,
                                               float* __restrict__ out) {
    __shared__ float ws[8][MAXNZ];
    int w8 = threadIdx.x >> 5, lane = threadIdx.x & 31;
    int warp = blockIdx.x * 8 + w8;
    int i = warp >> 2, h = warp & 3;
    int cnt = g_cnt[i];
    const int* cp = g_col + i * MAXNZ;
    float eli = el[i * 4 + h];
    // phase 1: edge scores + warp softmax (registers)
    float ew[4];
    float m = -1e30f;
#pragma unroll
    for (int kk = 0; kk < 4; kk++) {
        int k = kk * 32 + lane;
        float e = -1e30f;
        if (k < cnt) {
            int j = cp[k];
            e = eli + er[j * 4 + h];
            e = (e >= 0.f) ? e : ALPHA * e;
        }
        ew[kk] = e;
        m = fmaxf(m, e);
    }
#pragma unroll
    for (int o = 16; o > 0; o >>= 1) m = fmaxf(m, __shfl_xor_sync(0xffffffffu, m, o));
    float s = 0.f;
#pragma unroll
    for (int kk = 0; kk < 4; kk++) {
        float v = __expf(ew[kk] - m);
        ew[kk] = v; s += v;
    }
#pragma unroll
    for (int o = 16; o > 0; o >>= 1) s += __shfl_xor_sync(0xffffffffu, s, o);
    float inv = 1.f / s;
#pragma unroll
    for (int kk = 0; kk < 4; kk++) ws[w8][kk * 32 + lane] = ew[kk] * inv;
    __syncwarp();
    // phase 2: aggregate (lane owns cols 2*lane, 2*lane+1 of this head)
    const float2* Wh2 = (const float2*)Wh;   // row stride 128 float2
    size_t coloff = (size_t)h * 32 + lane;
    float2 a0 = make_float2(0.f, 0.f), a1 = make_float2(0.f, 0.f);
    int k = 0;
    for (; k + 2 <= cnt; k += 2) {
        float w0 = ws[w8][k], w1 = ws[w8][k + 1];
        int j0 = cp[k], j1 = cp[k + 1];
        float2 v0 = Wh2[(size_t)j0 * 128 + coloff];
        float2 v1 = Wh2[(size_t)j1 * 128 + coloff];
        a0.x += w0 * v0.x; a0.y += w0 * v0.y;
        a1.x += w1 * v1.x; a1.y += w1 * v1.y;
    }
    if (k < cnt) {
        float w0 = ws[w8][k];
        float2 v0 = Wh2[(size_t)cp[k] * 128 + coloff];
        a0.x += w0 * v0.x; a0.y += w0 * v0.y;
    }
    float sx = a0.x + a1.x, sy = a0.y + a1.y;
    sx = (sx > 0.f) ? sx : (__expf(sx) - 1.f);
    sy = (sy > 0.f) ? sy : (__expf(sy) - 1.f);
    ((float2*)out)[(size_t)i * 128 + coloff] = make_float2(sx, sy);
}

// ---------------- att GAT: warp per row + fused t1 = gc @ W1 -----------------
__global__ __launch_bounds__(256) void k_gat1w(const float* __restrict__ Wh,
                                               const float* __restrict__ el2,
                                               const float* __restrict__ er2,
                                               const float* __restrict__ W1) {
    __shared__ float ws[8][MAXNZ];
    __shared__ float gcs[8][64];
    int w8 = threadIdx.x >> 5, lane = threadIdx.x & 31;
    int i = blockIdx.x * 8 + w8;
    int cnt = g_cnt[i];
    const int* cp = g_col + i * MAXNZ;
    float eli = el2[i];
    float ew[4];
    float m = -1e30f;
#pragma unroll
    for (int kk = 0; kk < 4; kk++) {
        int k = kk * 32 + lane;
        float e = -1e30f;
        if (k < cnt) {
            e = eli + er2[cp[k]];
            e = (e >= 0.f) ? e : ALPHA * e;
        }
        ew[kk] = e;
        m = fmaxf(m, e);
    }
#pragma unroll
    for (int o = 16; o > 0; o >>= 1) m = fmaxf(m, __shfl_xor_sync(0xffffffffu, m, o));
    float s = 0.f;
#pragma unroll
    for (int kk = 0; kk < 4; kk++) {
        float v = __expf(ew[kk] - m);
        ew[kk] = v; s += v;
    }
#pragma unroll
    for (int o = 16; o > 0; o >>= 1) s += __shfl_xor_sync(0xffffffffu, s, o);
    float inv = 1.f / s;
#pragma unroll
    for (int kk = 0; kk < 4; kk++) ws[w8][kk * 32 + lane] = ew[kk] * inv;
    __syncwarp();
    // aggregate: lane owns cols 2*lane, 2*lane+1 of 64
    const float2* Wh2 = (const float2*)Wh;   // row stride 32 float2
    float2 a0 = make_float2(0.f, 0.f), a1 = make_float2(0.f, 0.f);
    int k = 0;
    for (; k + 2 <= cnt; k += 2) {
        float w0 = ws[w8][k], w1 = ws[w8][k + 1];
        int j0 = cp[k], j1 = cp[k + 1];
        float2 v0 = Wh2[(size_t)j0 * 32 + lane];
        float2 v1 = Wh2[(size_t)j1 * 32 + lane];
        a0.x += w0 * v0.x; a0.y += w0 * v0.y;
        a1.x += w1 * v1.x; a1.y += w1 * v1.y;
    }
    if (k < cnt) {
        float w0 = ws[w8][k];
        float2 v0 = Wh2[(size_t)cp[k] * 32 + lane];
        a0.x += w0 * v0.x; a0.y += w0 * v0.y;
    }
    float sx = a0.x + a1.x, sy = a0.y + a1.y;
    sx = (sx > 0.f) ? sx : (__expf(sx) - 1.f);
    sy = (sy > 0.f) ? sy : (__expf(sy) - 1.f);
    gcs[w8][lane * 2] = sx;
    gcs[w8][lane * 2 + 1] = sy;
    __syncwarp();
    // t1 row = gc_row @ W1 [64 x 32]; lane owns output col `lane`
    float acc = 0.f;
#pragma unroll 16
    for (int kk = 0; kk < 64; kk++) acc += gcs[w8][kk] * W1[kk * 32 + lane];
    g_t1[i * 32 + lane] = acc;
}

// ---------------- h1 = relu(adj @ t1) fused with t23 = h1 @ [W2|W3] ----------
__global__ void k_spmm_t23(const float* __restrict__ W2, const float* __restrict__ W3) {
    __shared__ float Bs[32 * 32];
    int tid = threadIdx.x;
    for (int idx = tid; idx < 32 * 16; idx += 256) {
        int k = idx >> 4, c = idx & 15;
        Bs[k * 32 + c]      = W2[idx];
        Bs[k * 32 + 16 + c] = W3[idx];
    }
    __syncthreads();
    int r = blockIdx.x * 8 + (tid >> 5);
    int lane = tid & 31;
    int cnt = g_cnt[r];
    const int* cp = g_col + r * MAXNZ;
    float acc = 0.f;
    int k = 0;
    for (; k + 4 <= cnt; k += 4) {
        int j0 = cp[k], j1 = cp[k + 1], j2 = cp[k + 2], j3 = cp[k + 3];
        acc += g_t1[j0 * 32 + lane] + g_t1[j1 * 32 + lane]
             + g_t1[j2 * 32 + lane] + g_t1[j3 * 32 + lane];
    }
    for (; k < cnt; k++) acc += g_t1[cp[k] * 32 + lane];
    acc = fmaxf(acc, 0.f);
    float s = 0.f;
#pragma unroll
    for (int kk = 0; kk < 32; kk++) {
        float hk = __shfl_sync(0xffffffffu, acc, kk);
        s += hk * Bs[kk * 32 + lane];
    }
    g_t23[r * 32 + lane] = s;
}

// ---------------- mu/logvar spmm + reparameterize ----------------------------
__global__ void k_mlz(const float* __restrict__ eps, float* __restrict__ out) {
    int tid = threadIdx.x;
    int r = blockIdx.x * 8 + (tid >> 5);
    int lane = tid & 31;
    int cnt = g_cnt[r];
    const int* cp = g_col + r * MAXNZ;
    float acc = 0.f;
    int k = 0;
    for (; k + 4 <= cnt; k += 4) {
        int j0 = cp[k], j1 = cp[k + 1], j2 = cp[k + 2], j3 = cp[k + 3];
        acc += g_t23[j0 * 32 + lane] + g_t23[j1 * 32 + lane]
             + g_t23[j2 * 32 + lane] + g_t23[j3 * 32 + lane];
    }
    for (; k < cnt; k++) acc += g_t23[cp[k] * 32 + lane];
    float other = __shfl_xor_sync(0xffffffffu, acc, 16);
    const size_t NN = (size_t)NV * NV;
    if (lane < 16) {
        float mu = acc, lv = other;
        float z = eps[r * 16 + lane] * expf(lv) + mu;
        g_z[r * 16 + lane] = z;
        out[NN + (size_t)r * 16 + lane] = mu;
    } else {
        out[NN + (size_t)NV * 16 + (size_t)r * 16 + (lane - 16)] = acc;
    }
}

// ---------------- adj_rec = z @ z^T : 128x128 tile, 8x8 micro, f32x2 ---------
__global__ __launch_bounds__(256) void k_zz(float* __restrict__ out) {
    int m0 = blockIdx.y * 128, n0 = blockIdx.x * 128;
    __shared__ float zr[16][128];
    __shared__ float zc[16][128];
    int tid = threadIdx.x;
    const float4* z4 = (const float4*)g_z;
#pragma unroll
    for (int t = tid; t < 512; t += 256) {
        int r = t >> 2, c4 = (t & 3) * 4;
        float4 v = z4[(size_t)(m0 + r) * 4 + (t & 3)];
        zr[c4][r] = v.x; zr[c4 + 1][r] = v.y; zr[c4 + 2][r] = v.z; zr[c4 + 3][r] = v.w;
        float4 w = z4[(size_t)(n0 + r) * 4 + (t & 3)];
        zc[c4][r] = w.x; zc[c4 + 1][r] = w.y; zc[c4 + 2][r] = w.z; zc[c4 + 3][r] = w.w;
    }
    __syncthreads();
    int tx = tid & 15, ty = tid >> 4;
    unsigned long long acc2[8][4] = {};
#pragma unroll
    for (int kk = 0; kk < 16; kk++) {
        float4 b0 = *(float4*)&zc[kk][tx * 8];
        float4 b1 = *(float4*)&zc[kk][tx * 8 + 4];
        unsigned long long pb0 = pack2(b0.x, b0.y), pb1 = pack2(b0.z, b0.w);
        unsigned long long pb2 = pack2(b1.x, b1.y), pb3 = pack2(b1.z, b1.w);
        float4 a0 = *(float4*)&zr[kk][ty * 8];
        float4 a1 = *(float4*)&zr[kk][ty * 8 + 4];
        float av[8] = {a0.x, a0.y, a0.z, a0.w, a1.x, a1.y, a1.z, a1.w};
#pragma unroll
        for (int i = 0; i < 8; i++) {
            unsigned long long ai = pack2(av[i], av[i]);
            ffma2(acc2[i][0], ai, pb0);
            ffma2(acc2[i][1], ai, pb1);
            ffma2(acc2[i][2], ai, pb2);
            ffma2(acc2[i][3], ai, pb3);
        }
    }
#pragma unroll
    for (int i = 0; i < 8; i++) {
        float2 c0 = unpack2(acc2[i][0]), c1 = unpack2(acc2[i][1]);
        float2 c2 = unpack2(acc2[i][2]), c3 = unpack2(acc2[i][3]);
        float* op = out + (size_t)(m0 + ty * 8 + i) * NV + n0 + tx * 8;
        *(float4*)op       = make_float4(c0.x, c0.y, c1.x, c1.y);
        *(float4*)(op + 4) = make_float4(c2.x, c2.y, c3.x, c3.y);
    }
}

// ---------------- launch (single stream) --------------------------------------
extern "C" void kernel_launch(void* const* d_in, const int* in_sizes, int n_in,
                              void* d_out, int out_size) {
    const float* x       = (const float*)d_in[0];
    const float* adj     = (const float*)d_in[1];
    const float* W_heads = (const float*)d_in[2];
    const float* a_heads = (const float*)d_in[3];
    const float* W_att   = (const float*)d_in[4];
    const float* a_att   = (const float*)d_in[5];
    const float* W1      = (const float*)d_in[6];
    const float* W2      = (const float*)d_in[7];
    const float* W3      = (const float*)d_in[8];
    const float* eps     = (const float*)d_in[9];
    float* out = (float*)d_out;

    float *p_Whcat, *p_cat, *p_Whc, *p_el, *p_er, *p_el2, *p_er2;
    cudaGetSymbolAddress((void**)&p_Whcat, g_Whcat);
    cudaGetSymbolAddress((void**)&p_cat,   g_cat);
    cudaGetSymbolAddress((void**)&p_Whc,   g_Whc);
    cudaGetSymbolAddress((void**)&p_el,    g_el);
    cudaGetSymbolAddress((void**)&p_er,    g_er);
    cudaGetSymbolAddress((void**)&p_el2,   g_el2);
    cudaGetSymbolAddress((void**)&p_er2,   g_er2);

    // 1. CSR of adj
    k_csr<<<NV / 8, 256>>>(adj);
    // 2. Wh for all heads + fused el/er  (BM=32 -> 512 blocks)
    k_gemm<4><<<dim3(NV / 32, HV), 128>>>(x, W_heads, p_Whcat, DV, HF, DV * F1V, F1V,
                                          a_heads, 2 * F1V, p_el, p_er, HV);
    // 3. multi-head GAT aggregate -> cat  (warp per (row, head))
    k_gat4w<<<NV * HV / 8, 256>>>(p_Whcat, p_el, p_er, p_cat);
    // 4. Whc = cat @ W_att + fused el2/er2  (BM=8 -> 512 blocks)
    k_gemm<1><<<dim3(NV / 8, 1), 128>>>(p_cat, W_att, p_Whc, HF, F1V, 0, 0,
                                        a_att, 0, p_el2, p_er2, 1);
    // 5. attention-level GAT + fused t1  (warp per row)
    k_gat1w<<<NV / 8, 256>>>(p_Whc, p_el2, p_er2, W1);
    // 6. h1 = relu(adj@t1) + fused t23
    k_spmm_t23<<<NV / 8, 256>>>(W2, W3);
    // 7. mu/logvar spmm + reparameterize
    k_mlz<<<NV / 8, 256>>>(eps, out);
    // 8. adj_rec = z @ z^T
    k_zz<<<dim3(NV / 128, NV / 128), 256>>>(out);
}

// round 10
// speedup vs baseline: 1.5446x; 1.0792x over previous
#include <cuda_runtime.h>
#include <cstdint>

#define NV   4096
#define DV   512
#define F1V  64
#define HV   4
#define HF   256   // H*F1
#define MAXNZ 128
#define ALPHA 0.2f

// ---------------- scratch (device globals; no allocs allowed) ----------------
__device__ int   g_col[NV * MAXNZ];
__device__ int   g_cnt[NV];
__device__ float g_Whcat[NV * HF];   // x @ W_heads (head h in cols [h*64,(h+1)*64))
__device__ float g_cat[NV * HF];     // multi-head GAT output (elu'd, concat)
__device__ float g_Whc[NV * F1V];    // cat @ W_att
__device__ float g_el[NV * HV];      // [i][h]
__device__ float g_er[NV * HV];
__device__ float g_el2[NV];
__device__ float g_er2[NV];
__device__ float g_t1[NV * 32];
__device__ float g_t23[NV * 32];     // [mu-pre | logvar-pre] per row (16+16)
__device__ float g_z[NV * 16];

// ---------------- f32x2 packed-FMA helpers (ptxas won't auto-fuse) -----------
__device__ __forceinline__ unsigned long long pack2(float lo, float hi) {
    unsigned long long r;
    asm("mov.b64 %0, {%1, %2};" : "=l"(r) : "f"(lo), "f"(hi));
    return r;
}
__device__ __forceinline__ void ffma2(unsigned long long& d, unsigned long long a,
                                      unsigned long long b) {
    asm("fma.rn.f32x2 %0, %1, %2, %0;" : "+l"(d) : "l"(a), "l"(b));
}
__device__ __forceinline__ float2 unpack2(unsigned long long v) {
    float2 f;
    asm("mov.b64 {%0, %1}, %2;" : "=f"(f.x), "=f"(f.y) : "l"(v));
    return f;
}

// ---------------- CSR build: warp per row, float4 stream ---------------------
__global__ void k_csr(const float* __restrict__ adj) {
    int wid = threadIdx.x >> 5, lane = threadIdx.x & 31;
    int row = blockIdx.x * 8 + wid;
    const float4* r4 = (const float4*)(adj + (size_t)row * NV);
    unsigned lm = (1u << lane) - 1u;
    int base = 0;
    int* cp = g_col + row * MAXNZ;
#pragma unroll 4
    for (int c0 = 0; c0 < NV / 4; c0 += 32) {
        float4 v = r4[c0 + lane];
        unsigned b0 = __ballot_sync(0xffffffffu, v.x > 0.f);
        unsigned b1 = __ballot_sync(0xffffffffu, v.y > 0.f);
        unsigned b2 = __ballot_sync(0xffffffffu, v.z > 0.f);
        unsigned b3 = __ballot_sync(0xffffffffu, v.w > 0.f);
        int t0 = __popc(b0), t1 = __popc(b1), t2 = __popc(b2), t3 = __popc(b3);
        int col = (c0 + lane) * 4;
        if (v.x > 0.f) { int p = base + __popc(b0 & lm);                if (p < MAXNZ) cp[p] = col; }
        if (v.y > 0.f) { int p = base + t0 + __popc(b1 & lm);           if (p < MAXNZ) cp[p] = col + 1; }
        if (v.z > 0.f) { int p = base + t0 + t1 + __popc(b2 & lm);      if (p < MAXNZ) cp[p] = col + 2; }
        if (v.w > 0.f) { int p = base + t0 + t1 + t2 + __popc(b3 & lm); if (p < MAXNZ) cp[p] = col + 3; }
        base += t0 + t1 + t2 + t3;
    }
    if (lane == 0) g_cnt[row] = (base < MAXNZ) ? base : MAXNZ;
}

// ---------------- heads GEMM: BM=32 x 64, reg double-buffered, f32x2 ---------
// C[m0:+32, h*64:+64] = A[M,K] @ B_h[K,64] ; fused el/er epilogue.
__global__ __launch_bounds__(128) void k_gemm4(const float* __restrict__ A,
                                               const float* __restrict__ Bbase,
                                               float* __restrict__ Cbase,
                                               int K, int ldc, int bstride, int ccoloff,
                                               const float* __restrict__ avec, int avstride,
                                               float* __restrict__ el_out,
                                               float* __restrict__ er_out, int estr) {
    const int RM = 4, BM = 32;
    int h = blockIdx.y;
    const float* B = Bbase + (size_t)h * bstride;
    int m0 = blockIdx.x * BM;
    int tid = threadIdx.x;
    int tx = tid & 15, ty = tid >> 4;
    __shared__ float As[16][BM];
    __shared__ float Bs[16][64];
    unsigned long long acc2[RM][2] = {};
    // per-thread load indices
    int ar = tid >> 2, ac4 = (tid & 3) * 4;            // A: 1 float4
    int br = tid >> 4, bc = (tid & 15) * 4;            // B: 2 float4 (rows br, br+8)
    float4 rA, rB0, rB1;
    rA  = *(const float4*)(A + (size_t)(m0 + ar) * K + ac4);
    rB0 = *(const float4*)(B + (size_t)br * 64 + bc);
    rB1 = *(const float4*)(B + (size_t)(br + 8) * 64 + bc);
    for (int k0 = 0; k0 < K; k0 += 16) {
        __syncthreads();
        As[ac4][ar] = rA.x; As[ac4 + 1][ar] = rA.y;
        As[ac4 + 2][ar] = rA.z; As[ac4 + 3][ar] = rA.w;
        *(float4*)&Bs[br][bc] = rB0;
        *(float4*)&Bs[br + 8][bc] = rB1;
        __syncthreads();
        if (k0 + 16 < K) {
            rA  = *(const float4*)(A + (size_t)(m0 + ar) * K + k0 + 16 + ac4);
            rB0 = *(const float4*)(B + (size_t)(k0 + 16 + br) * 64 + bc);
            rB1 = *(const float4*)(B + (size_t)(k0 + 24 + br) * 64 + bc);
        }
#pragma unroll
        for (int kk = 0; kk < 16; kk++) {
            float4 b = *(float4*)&Bs[kk][tx * 4];
            unsigned long long b01 = pack2(b.x, b.y), b23 = pack2(b.z, b.w);
            float4 a = *(float4*)&As[kk][ty * 4];
            float av[4] = {a.x, a.y, a.z, a.w};
#pragma unroll
            for (int i = 0; i < RM; i++) {
                unsigned long long ai = pack2(av[i], av[i]);
                ffma2(acc2[i][0], ai, b01);
                ffma2(acc2[i][1], ai, b23);
            }
        }
    }
    int coff = h * ccoloff;
    float4 aL = *(const float4*)(avec + (size_t)h * avstride + tx * 4);
    float4 aR = *(const float4*)(avec + (size_t)h * avstride + 64 + tx * 4);
#pragma unroll
    for (int i = 0; i < RM; i++) {
        float2 c0 = unpack2(acc2[i][0]), c1 = unpack2(acc2[i][1]);
        *(float4*)(Cbase + (size_t)(m0 + ty * RM + i) * ldc + coff + tx * 4)
            = make_float4(c0.x, c0.y, c1.x, c1.y);
        float sl = c0.x * aL.x + c0.y * aL.y + c1.x * aL.z + c1.y * aL.w;
        float sr = c0.x * aR.x + c0.y * aR.y + c1.x * aR.z + c1.y * aR.w;
#pragma unroll
        for (int o = 8; o > 0; o >>= 1) {
            sl += __shfl_xor_sync(0xffffffffu, sl, o);
            sr += __shfl_xor_sync(0xffffffffu, sr, o);
        }
        if (tx == 0) {
            int row = m0 + ty * RM + i;
            el_out[row * estr + h] = sl;
            er_out[row * estr + h] = sr;
        }
    }
}

// ---------------- att GEMM: W_att resident in smem, warp = 2 rows ------------
// C[4096,64] = cat[4096,256] @ W[256,64]; fused el2/er2. One barrier per block.
__global__ __launch_bounds__(256) void k_attgemm(const float* __restrict__ A,
                                                 const float* __restrict__ W,
                                                 const float* __restrict__ avec,
                                                 float* __restrict__ C,
                                                 float* __restrict__ el2,
                                                 float* __restrict__ er2) {
    extern __shared__ float sm[];
    float* Ws = sm;                 // [256][64]
    float* As = sm + 256 * 64;      // [16][256]
    int tid = threadIdx.x;
    const float4* W4 = (const float4*)W;
    float4* Ws4 = (float4*)Ws;
#pragma unroll
    for (int t = 0; t < 16; t++) Ws4[tid + t * 256] = W4[tid + t * 256];
    int r0 = blockIdx.x * 16;
    const float4* A4 = (const float4*)(A + (size_t)r0 * 256);
    float4* As4 = (float4*)As;
#pragma unroll
    for (int t = 0; t < 4; t++) As4[tid + t * 256] = A4[tid + t * 256];
    __syncthreads();
    int w8 = tid >> 5, lane = tid & 31;
    const float* ar0 = As + (w8 * 2) * 256;
    const float* ar1 = ar0 + 256;
    const float2* Wl = (const float2*)(Ws) + lane;   // Ws[k][2*lane] as float2
    float2 p00 = {0.f, 0.f}, p01 = {0.f, 0.f};       // row0 partials
    float2 p10 = {0.f, 0.f}, p11 = {0.f, 0.f};       // row1 partials
#pragma unroll 4
    for (int k = 0; k < 256; k += 4) {
        float4 a0 = *(const float4*)(ar0 + k);
        float4 a1 = *(const float4*)(ar1 + k);
        float2 w0 = Wl[(k)     * 32];
        float2 w1 = Wl[(k + 1) * 32];
        float2 w2 = Wl[(k + 2) * 32];
        float2 w3 = Wl[(k + 3) * 32];
        p00.x += a0.x * w0.x; p00.y += a0.x * w0.y;
        p01.x += a0.y * w1.x; p01.y += a0.y * w1.y;
        p00.x += a0.z * w2.x; p00.y += a0.z * w2.y;
        p01.x += a0.w * w3.x; p01.y += a0.w * w3.y;
        p10.x += a1.x * w0.x; p10.y += a1.x * w0.y;
        p11.x += a1.y * w1.x; p11.y += a1.y * w1.y;
        p10.x += a1.z * w2.x; p10.y += a1.z * w2.y;
        p11.x += a1.w * w3.x; p11.y += a1.w * w3.y;
    }
    float2 aL = *(const float2*)(avec + 2 * lane);
    float2 aR = *(const float2*)(avec + 64 + 2 * lane);
#pragma unroll
    for (int r = 0; r < 2; r++) {
        float2 acc = (r == 0) ? make_float2(p00.x + p01.x, p00.y + p01.y)
                              : make_float2(p10.x + p11.x, p10.y + p11.y);
        int row = r0 + w8 * 2 + r;
        ((float2*)C)[(size_t)row * 32 + lane] = acc;
        float sl = acc.x * aL.x + acc.y * aL.y;
        float sr = acc.x * aR.x + acc.y * aR.y;
#pragma unroll
        for (int o = 16; o > 0; o >>= 1) {
            sl += __shfl_xor_sync(0xffffffffu, sl, o);
            sr += __shfl_xor_sync(0xffffffffu, sr, o);
        }
        if (lane == 0) { el2[row] = sl; er2[row] = sr; }
    }
}

// ---------------- 4-head GAT: warp per (row, head), no block syncs -----------
__global__ __launch_bounds__(256) void k_gat4w(const float* __restrict__ Wh,
                                               const float* __restrict__ el,
                                               const float* __restrict__ er,
                                               float* __restrict__ out) {
    __shared__ float ws[8][MAXNZ];
    int w8 = threadIdx.x >> 5, lane = threadIdx.x & 31;
    int warp = blockIdx.x * 8 + w8;
    int i = warp >> 2, h = warp & 3;
    int cnt = g_cnt[i];
    const int* cp = g_col + i * MAXNZ;
    float eli = el[i * 4 + h];
    float ew[4];
    float m = -1e30f;
#pragma unroll
    for (int kk = 0; kk < 4; kk++) {
        int k = kk * 32 + lane;
        float e = -1e30f;
        if (k < cnt) {
            int j = cp[k];
            e = eli + er[j * 4 + h];
            e = (e >= 0.f) ? e : ALPHA * e;
        }
        ew[kk] = e;
        m = fmaxf(m, e);
    }
#pragma unroll
    for (int o = 16; o > 0; o >>= 1) m = fmaxf(m, __shfl_xor_sync(0xffffffffu, m, o));
    float s = 0.f;
#pragma unroll
    for (int kk = 0; kk < 4; kk++) {
        float v = __expf(ew[kk] - m);
        ew[kk] = v; s += v;
    }
#pragma unroll
    for (int o = 16; o > 0; o >>= 1) s += __shfl_xor_sync(0xffffffffu, s, o);
    float inv = 1.f / s;
#pragma unroll
    for (int kk = 0; kk < 4; kk++) ws[w8][kk * 32 + lane] = ew[kk] * inv;
    __syncwarp();
    const float2* Wh2 = (const float2*)Wh;   // row stride 128 float2
    size_t coloff = (size_t)h * 32 + lane;
    float2 a0 = make_float2(0.f, 0.f), a1 = make_float2(0.f, 0.f);
    int k = 0;
    for (; k + 2 <= cnt; k += 2) {
        float w0 = ws[w8][k], w1 = ws[w8][k + 1];
        int j0 = cp[k], j1 = cp[k + 1];
        float2 v0 = Wh2[(size_t)j0 * 128 + coloff];
        float2 v1 = Wh2[(size_t)j1 * 128 + coloff];
        a0.x += w0 * v0.x; a0.y += w0 * v0.y;
        a1.x += w1 * v1.x; a1.y += w1 * v1.y;
    }
    if (k < cnt) {
        float w0 = ws[w8][k];
        float2 v0 = Wh2[(size_t)cp[k] * 128 + coloff];
        a0.x += w0 * v0.x; a0.y += w0 * v0.y;
    }
    float sx = a0.x + a1.x, sy = a0.y + a1.y;
    sx = (sx > 0.f) ? sx : (__expf(sx) - 1.f);
    sy = (sy > 0.f) ? sy : (__expf(sy) - 1.f);
    ((float2*)out)[(size_t)i * 128 + coloff] = make_float2(sx, sy);
}

// ---------------- att GAT: warp per row + fused t1 = gc @ W1 -----------------
__global__ __launch_bounds__(256) void k_gat1w(const float* __restrict__ Wh,
                                               const float* __restrict__ el2,
                                               const float* __restrict__ er2,
                                               const float* __restrict__ W1) {
    __shared__ float ws[8][MAXNZ];
    __shared__ float gcs[8][64];
    int w8 = threadIdx.x >> 5, lane = threadIdx.x & 31;
    int i = blockIdx.x * 8 + w8;
    int cnt = g_cnt[i];
    const int* cp = g_col + i * MAXNZ;
    float eli = el2[i];
    float ew[4];
    float m = -1e30f;
#pragma unroll
    for (int kk = 0; kk < 4; kk++) {
        int k = kk * 32 + lane;
        float e = -1e30f;
        if (k < cnt) {
            e = eli + er2[cp[k]];
            e = (e >= 0.f) ? e : ALPHA * e;
        }
        ew[kk] = e;
        m = fmaxf(m, e);
    }
#pragma unroll
    for (int o = 16; o > 0; o >>= 1) m = fmaxf(m, __shfl_xor_sync(0xffffffffu, m, o));
    float s = 0.f;
#pragma unroll
    for (int kk = 0; kk < 4; kk++) {
        float v = __expf(ew[kk] - m);
        ew[kk] = v; s += v;
    }
#pragma unroll
    for (int o = 16; o > 0; o >>= 1) s += __shfl_xor_sync(0xffffffffu, s, o);
    float inv = 1.f / s;
#pragma unroll
    for (int kk = 0; kk < 4; kk++) ws[w8][kk * 32 + lane] = ew[kk] * inv;
    __syncwarp();
    const float2* Wh2 = (const float2*)Wh;   // row stride 32 float2
    float2 a0 = make_float2(0.f, 0.f), a1 = make_float2(0.f, 0.f);
    int k = 0;
    for (; k + 2 <= cnt; k += 2) {
        float w0 = ws[w8][k], w1 = ws[w8][k + 1];
        int j0 = cp[k], j1 = cp[k + 1];
        float2 v0 = Wh2[(size_t)j0 * 32 + lane];
        float2 v1 = Wh2[(size_t)j1 * 32 + lane];
        a0.x += w0 * v0.x; a0.y += w0 * v0.y;
        a1.x += w1 * v1.x; a1.y += w1 * v1.y;
    }
    if (k < cnt) {
        float w0 = ws[w8][k];
        float2 v0 = Wh2[(size_t)cp[k] * 32 + lane];
        a0.x += w0 * v0.x; a0.y += w0 * v0.y;
    }
    float sx = a0.x + a1.x, sy = a0.y + a1.y;
    sx = (sx > 0.f) ? sx : (__expf(sx) - 1.f);
    sy = (sy > 0.f) ? sy : (__expf(sy) - 1.f);
    gcs[w8][lane * 2] = sx;
    gcs[w8][lane * 2 + 1] = sy;
    __syncwarp();
    float acc = 0.f;
#pragma unroll 16
    for (int kk = 0; kk < 64; kk++) acc += gcs[w8][kk] * W1[kk * 32 + lane];
    g_t1[i * 32 + lane] = acc;
}

// ---------------- h1 = relu(adj @ t1) fused with t23 = h1 @ [W2|W3] ----------
__global__ void k_spmm_t23(const float* __restrict__ W2, const float* __restrict__ W3) {
    __shared__ float Bs[32 * 32];
    int tid = threadIdx.x;
    for (int idx = tid; idx < 32 * 16; idx += 256) {
        int k = idx >> 4, c = idx & 15;
        Bs[k * 32 + c]      = W2[idx];
        Bs[k * 32 + 16 + c] = W3[idx];
    }
    __syncthreads();
    int r = blockIdx.x * 8 + (tid >> 5);
    int lane = tid & 31;
    int cnt = g_cnt[r];
    const int* cp = g_col + r * MAXNZ;
    float acc = 0.f;
    int k = 0;
    for (; k + 4 <= cnt; k += 4) {
        int j0 = cp[k], j1 = cp[k + 1], j2 = cp[k + 2], j3 = cp[k + 3];
        acc += g_t1[j0 * 32 + lane] + g_t1[j1 * 32 + lane]
             + g_t1[j2 * 32 + lane] + g_t1[j3 * 32 + lane];
    }
    for (; k < cnt; k++) acc += g_t1[cp[k] * 32 + lane];
    acc = fmaxf(acc, 0.f);
    float s = 0.f;
#pragma unroll
    for (int kk = 0; kk < 32; kk++) {
        float hk = __shfl_sync(0xffffffffu, acc, kk);
        s += hk * Bs[kk * 32 + lane];
    }
    g_t23[r * 32 + lane] = s;
}

// ---------------- mu/logvar spmm + reparameterize ----------------------------
__global__ void k_mlz(const float* __restrict__ eps, float* __restrict__ out) {
    int tid = threadIdx.x;
    int r = blockIdx.x * 8 + (tid >> 5);
    int lane = tid & 31;
    int cnt = g_cnt[r];
    const int* cp = g_col + r * MAXNZ;
    float acc = 0.f;
    int k = 0;
    for (; k + 4 <= cnt; k += 4) {
        int j0 = cp[k], j1 = cp[k + 1], j2 = cp[k + 2], j3 = cp[k + 3];
        acc += g_t23[j0 * 32 + lane] + g_t23[j1 * 32 + lane]
             + g_t23[j2 * 32 + lane] + g_t23[j3 * 32 + lane];
    }
    for (; k < cnt; k++) acc += g_t23[cp[k] * 32 + lane];
    float other = __shfl_xor_sync(0xffffffffu, acc, 16);
    const size_t NN = (size_t)NV * NV;
    if (lane < 16) {
        float mu = acc, lv = other;
        float z = eps[r * 16 + lane] * expf(lv) + mu;
        g_z[r * 16 + lane] = z;
        out[NN + (size_t)r * 16 + lane] = mu;
    } else {
        out[NN + (size_t)NV * 16 + (size_t)r * 16 + (lane - 16)] = acc;
    }
}

// ---------------- adj_rec = z @ z^T : 128x128 tile, 8x8 micro, f32x2 ---------
__global__ __launch_bounds__(256) void k_zz(float* __restrict__ out) {
    int m0 = blockIdx.y * 128, n0 = blockIdx.x * 128;
    __shared__ float zr[16][128];
    __shared__ float zc[16][128];
    int tid = threadIdx.x;
    const float4* z4 = (const float4*)g_z;
#pragma unroll
    for (int t = tid; t < 512; t += 256) {
        int r = t >> 2, c4 = (t & 3) * 4;
        float4 v = z4[(size_t)(m0 + r) * 4 + (t & 3)];
        zr[c4][r] = v.x; zr[c4 + 1][r] = v.y; zr[c4 + 2][r] = v.z; zr[c4 + 3][r] = v.w;
        float4 w = z4[(size_t)(n0 + r) * 4 + (t & 3)];
        zc[c4][r] = w.x; zc[c4 + 1][r] = w.y; zc[c4 + 2][r] = w.z; zc[c4 + 3][r] = w.w;
    }
    __syncthreads();
    int tx = tid & 15, ty = tid >> 4;
    unsigned long long acc2[8][4] = {};
#pragma unroll
    for (int kk = 0; kk < 16; kk++) {
        float4 b0 = *(float4*)&zc[kk][tx * 8];
        float4 b1 = *(float4*)&zc[kk][tx * 8 + 4];
        unsigned long long pb0 = pack2(b0.x, b0.y), pb1 = pack2(b0.z, b0.w);
        unsigned long long pb2 = pack2(b1.x, b1.y), pb3 = pack2(b1.z, b1.w);
        float4 a0 = *(float4*)&zr[kk][ty * 8];
        float4 a1 = *(float4*)&zr[kk][ty * 8 + 4];
        float av[8] = {a0.x, a0.y, a0.z, a0.w, a1.x, a1.y, a1.z, a1.w};
#pragma unroll
        for (int i = 0; i < 8; i++) {
            unsigned long long ai = pack2(av[i], av[i]);
            ffma2(acc2[i][0], ai, pb0);
            ffma2(acc2[i][1], ai, pb1);
            ffma2(acc2[i][2], ai, pb2);
            ffma2(acc2[i][3], ai, pb3);
        }
    }
#pragma unroll
    for (int i = 0; i < 8; i++) {
        float2 c0 = unpack2(acc2[i][0]), c1 = unpack2(acc2[i][1]);
        float2 c2 = unpack2(acc2[i][2]), c3 = unpack2(acc2[i][3]);
        float* op = out + (size_t)(m0 + ty * 8 + i) * NV + n0 + tx * 8;
        *(float4*)op       = make_float4(c0.x, c0.y, c1.x, c1.y);
        *(float4*)(op + 4) = make_float4(c2.x, c2.y, c3.x, c3.y);
    }
}

// ---------------- launch (single stream) --------------------------------------
extern "C" void kernel_launch(void* const* d_in, const int* in_sizes, int n_in,
                              void* d_out, int out_size) {
    const float* x       = (const float*)d_in[0];
    const float* adj     = (const float*)d_in[1];
    const float* W_heads = (const float*)d_in[2];
    const float* a_heads = (const float*)d_in[3];
    const float* W_att   = (const float*)d_in[4];
    const float* a_att   = (const float*)d_in[5];
    const float* W1      = (const float*)d_in[6];
    const float* W2      = (const float*)d_in[7];
    const float* W3      = (const float*)d_in[8];
    const float* eps     = (const float*)d_in[9];
    float* out = (float*)d_out;

    float *p_Whcat, *p_cat, *p_Whc, *p_el, *p_er, *p_el2, *p_er2;
    cudaGetSymbolAddress((void**)&p_Whcat, g_Whcat);
    cudaGetSymbolAddress((void**)&p_cat,   g_cat);
    cudaGetSymbolAddress((void**)&p_Whc,   g_Whc);
    cudaGetSymbolAddress((void**)&p_el,    g_el);
    cudaGetSymbolAddress((void**)&p_er,    g_er);
    cudaGetSymbolAddress((void**)&p_el2,   g_el2);
    cudaGetSymbolAddress((void**)&p_er2,   g_er2);

    // opt-in smem for k_attgemm (host attr set once; not a device alloc)
    static bool attr_done = false;
    if (!attr_done) {
        cudaFuncSetAttribute(k_attgemm, cudaFuncAttributeMaxDynamicSharedMemorySize,
                             (256 * 64 + 16 * 256) * 4);
        attr_done = true;
    }

    // 1. CSR of adj
    k_csr<<<NV / 8, 256>>>(adj);
    // 2. Wh for all heads + fused el/er  (BM=32 -> 512 blocks, reg double-buffer)
    k_gemm4<<<dim3(NV / 32, HV), 128>>>(x, W_heads, p_Whcat, DV, HF, DV * F1V, F1V,
                                        a_heads, 2 * F1V, p_el, p_er, HV);
    // 3. multi-head GAT aggregate -> cat  (warp per (row, head))
    k_gat4w<<<NV * HV / 8, 256>>>(p_Whcat, p_el, p_er, p_cat);
    // 4. Whc = cat @ W_att + fused el2/er2  (W resident in smem)
    k_attgemm<<<NV / 16, 256, (256 * 64 + 16 * 256) * 4>>>(p_cat, W_att, a_att,
                                                           p_Whc, p_el2, p_er2);
    // 5. attention-level GAT + fused t1  (warp per row)
    k_gat1w<<<NV / 8, 256>>>(p_Whc, p_el2, p_er2, W1);
    // 6. h1 = relu(adj@t1) + fused t23
    k_spmm_t23<<<NV / 8, 256>>>(W2, W3);
    // 7. mu/logvar spmm + reparameterize
    k_mlz<<<NV / 8, 256>>>(eps, out);
    // 8. adj_rec = z @ z^T
    k_zz<<<dim3(NV / 128, NV / 128), 256>>>(out);
}